// round 1
// baseline (speedup 1.0000x reference)
#include <cuda_runtime.h>
#include <cuda_bf16.h>

#define N_MAX 50000
#define E_MAX 1600000
#define DIM 256
#define OUT 64
#define ALPHA 0.2f

// Scratch (device globals — no allocation allowed)
__device__ float g_h[N_MAX * OUT];      // h = x @ W
__device__ float g_s1[N_MAX];           // h[i] . a[:OUT]
__device__ float g_s2[N_MAX];           // h[i] . a[OUT:]
__device__ float g_rowsum[N_MAX];       // sum_j e_ij

// ---------------------------------------------------------------------------
// Zero d_out and rowsum
// ---------------------------------------------------------------------------
__global__ void zero_kernel(float* __restrict__ out, int n) {
    int i = blockIdx.x * blockDim.x + threadIdx.x;
    if (i < n * OUT) out[i] = 0.0f;
    if (i < n) g_rowsum[i] = 0.0f;
}

// ---------------------------------------------------------------------------
// h = x @ W   (x: [n,256], W: [256,64] row-major)
// 16 threads per row; each thread computes 4 consecutive outputs via float4.
// x load broadcasts across the 16 threads of a row; W float4 loads are
// perfectly coalesced and W (64KB) stays L1/L2 resident.
// ---------------------------------------------------------------------------
__global__ void gemm_kernel(const float* __restrict__ x,
                            const float* __restrict__ W,
                            int n) {
    int gid = blockIdx.x * blockDim.x + threadIdx.x;
    int row = gid >> 4;
    int o4  = (gid & 15) << 2;   // output column base (0,4,...,60)
    if (row >= n) return;

    const float4* x4 = reinterpret_cast<const float4*>(x + (size_t)row * DIM);

    float acc0 = 0.f, acc1 = 0.f, acc2 = 0.f, acc3 = 0.f;
#pragma unroll 4
    for (int d4 = 0; d4 < DIM / 4; d4++) {
        float4 xv = x4[d4];
        int d = d4 << 2;
        float4 w0 = *reinterpret_cast<const float4*>(W + (size_t)(d + 0) * OUT + o4);
        float4 w1 = *reinterpret_cast<const float4*>(W + (size_t)(d + 1) * OUT + o4);
        float4 w2 = *reinterpret_cast<const float4*>(W + (size_t)(d + 2) * OUT + o4);
        float4 w3 = *reinterpret_cast<const float4*>(W + (size_t)(d + 3) * OUT + o4);
        acc0 += xv.x * w0.x + xv.y * w1.x + xv.z * w2.x + xv.w * w3.x;
        acc1 += xv.x * w0.y + xv.y * w1.y + xv.z * w2.y + xv.w * w3.y;
        acc2 += xv.x * w0.z + xv.y * w1.z + xv.z * w2.z + xv.w * w3.z;
        acc3 += xv.x * w0.w + xv.y * w1.w + xv.z * w2.w + xv.w * w3.w;
    }
    float4 r = make_float4(acc0, acc1, acc2, acc3);
    *reinterpret_cast<float4*>(g_h + (size_t)row * OUT + o4) = r;
}

// ---------------------------------------------------------------------------
// Per-node scores: s1[i] = h[i].a[:64], s2[i] = h[i].a[64:]
// One warp per node; two h elements per lane; warp shuffle reduce.
// ---------------------------------------------------------------------------
__global__ void score_kernel(const float* __restrict__ a, int n) {
    int warp = (blockIdx.x * blockDim.x + threadIdx.x) >> 5;
    int lane = threadIdx.x & 31;
    if (warp >= n) return;

    float h0 = g_h[(size_t)warp * OUT + lane];
    float h1 = g_h[(size_t)warp * OUT + 32 + lane];
    float v1 = h0 * a[lane]      + h1 * a[32 + lane];
    float v2 = h0 * a[OUT + lane] + h1 * a[OUT + 32 + lane];
#pragma unroll
    for (int off = 16; off > 0; off >>= 1) {
        v1 += __shfl_down_sync(0xFFFFFFFFu, v1, off);
        v2 += __shfl_down_sync(0xFFFFFFFFu, v2, off);
    }
    if (lane == 0) {
        g_s1[warp] = v1;
        g_s2[warp] = v2;
    }
}

// ---------------------------------------------------------------------------
// Edge scatter: one warp per edge.
//   w = exp(-leakyrelu(s1[src] + s2[dst]))
//   out[src,:] += w * h[dst,:]   (64 floats, 2 per lane)
//   rowsum[src] += w
// ---------------------------------------------------------------------------
__global__ void edge_kernel(const int* __restrict__ ei,
                            float* __restrict__ out,
                            int e) {
    int warp = (blockIdx.x * blockDim.x + threadIdx.x) >> 5;
    int lane = threadIdx.x & 31;
    if (warp >= e) return;

    int src = ei[warp];
    int dst = ei[e + warp];

    float logit = g_s1[src] + g_s2[dst];
    float l = logit > 0.0f ? logit : ALPHA * logit;
    float w = __expf(-l);

    float v0 = g_h[(size_t)dst * OUT + lane];
    float v1 = g_h[(size_t)dst * OUT + 32 + lane];
    atomicAdd(&out[(size_t)src * OUT + lane],      w * v0);
    atomicAdd(&out[(size_t)src * OUT + 32 + lane], w * v1);
    if (lane == 0) atomicAdd(&g_rowsum[src], w);
}

// ---------------------------------------------------------------------------
// Finalize: out = elu(out / rowsum)
// ---------------------------------------------------------------------------
__global__ void finalize_kernel(float* __restrict__ out, int n) {
    int i = blockIdx.x * blockDim.x + threadIdx.x;
    if (i >= n * OUT) return;
    float r = g_rowsum[i >> 6];
    float v = out[i] / r;
    out[i] = v > 0.0f ? v : expm1f(v);
}

extern "C" void kernel_launch(void* const* d_in, const int* in_sizes, int n_in,
                              void* d_out, int out_size) {
    const float* x  = (const float*)d_in[0];
    const int*   ei = (const int*)d_in[1];
    const float* W  = (const float*)d_in[2];
    const float* a  = (const float*)d_in[3];
    float* out = (float*)d_out;

    int n = in_sizes[0] / DIM;   // 50000
    int e = in_sizes[1] / 2;     // 1600000

    // 1. zero out + rowsum
    {
        int total = n * OUT;
        zero_kernel<<<(total + 255) / 256, 256>>>(out, n);
    }
    // 2. h = x @ W
    {
        int threads = n * 16;
        gemm_kernel<<<(threads + 255) / 256, 256>>>(x, W, n);
    }
    // 3. per-node scores
    {
        int threads = n * 32;
        score_kernel<<<(threads + 255) / 256, 256>>>(a, n);
    }
    // 4. edge scatter (warp per edge)
    {
        long long threads = (long long)e * 32;
        int blocks = (int)((threads + 255) / 256);
        edge_kernel<<<blocks, 256>>>(ei, out, e);
    }
    // 5. finalize
    {
        int total = n * OUT;
        finalize_kernel<<<(total + 255) / 256, 256>>>(out, n);
    }
}

// round 2
// speedup vs baseline: 1.3746x; 1.3746x over previous
#include <cuda_runtime.h>
#include <cuda_bf16.h>

#define N_MAX 50000
#define E_MAX 1600000
#define DIM 256
#define OUT 64
#define ALPHA 0.2f
#define SCAN_B 1024
#define MAX_SCAN_BLOCKS ((N_MAX + SCAN_B - 1) / SCAN_B)

// Scratch (device globals — no allocation allowed)
__device__ float  g_h[N_MAX * OUT];          // h = x @ W
__device__ float  g_s1[N_MAX];               // h[i] . a[:OUT]
__device__ float  g_s2[N_MAX];               // h[i] . a[OUT:]
__device__ int    g_deg[N_MAX];              // histogram, then scatter cursor, then length
__device__ int    g_off[N_MAX];              // CSR exclusive offsets
__device__ int    g_blksum[MAX_SCAN_BLOCKS]; // scan partials
__device__ float2 g_csr[E_MAX];              // (dst as bits, weight) sorted by src

// ---------------------------------------------------------------------------
// Zero degree counters
// ---------------------------------------------------------------------------
__global__ void zero_deg_kernel(int n) {
    int i = blockIdx.x * blockDim.x + threadIdx.x;
    if (i < n) g_deg[i] = 0;
}

// ---------------------------------------------------------------------------
// h = x @ W (+ fused attention scores s1, s2)
// 16 threads per row; each thread computes 4 consecutive outputs via float4.
// ---------------------------------------------------------------------------
__global__ void gemm_kernel(const float* __restrict__ x,
                            const float* __restrict__ W,
                            const float* __restrict__ a,
                            int n) {
    int gid = blockIdx.x * blockDim.x + threadIdx.x;
    int row = gid >> 4;
    int o4  = (gid & 15) << 2;   // output column base (0,4,...,60)
    if (row >= n) return;

    const float4* x4 = reinterpret_cast<const float4*>(x + (size_t)row * DIM);

    float acc0 = 0.f, acc1 = 0.f, acc2 = 0.f, acc3 = 0.f;
#pragma unroll 4
    for (int d4 = 0; d4 < DIM / 4; d4++) {
        float4 xv = x4[d4];
        int d = d4 << 2;
        float4 w0 = *reinterpret_cast<const float4*>(W + (size_t)(d + 0) * OUT + o4);
        float4 w1 = *reinterpret_cast<const float4*>(W + (size_t)(d + 1) * OUT + o4);
        float4 w2 = *reinterpret_cast<const float4*>(W + (size_t)(d + 2) * OUT + o4);
        float4 w3 = *reinterpret_cast<const float4*>(W + (size_t)(d + 3) * OUT + o4);
        acc0 += xv.x * w0.x + xv.y * w1.x + xv.z * w2.x + xv.w * w3.x;
        acc1 += xv.x * w0.y + xv.y * w1.y + xv.z * w2.y + xv.w * w3.y;
        acc2 += xv.x * w0.z + xv.y * w1.z + xv.z * w2.z + xv.w * w3.z;
        acc3 += xv.x * w0.w + xv.y * w1.w + xv.z * w2.w + xv.w * w3.w;
    }
    *reinterpret_cast<float4*>(g_h + (size_t)row * OUT + o4) =
        make_float4(acc0, acc1, acc2, acc3);

    // Fused score: s1[row] = h[row].a[:64], s2[row] = h[row].a[64:]
    float4 a1 = *reinterpret_cast<const float4*>(a + o4);
    float4 a2 = *reinterpret_cast<const float4*>(a + OUT + o4);
    float p1 = acc0 * a1.x + acc1 * a1.y + acc2 * a1.z + acc3 * a1.w;
    float p2 = acc0 * a2.x + acc1 * a2.y + acc2 * a2.z + acc3 * a2.w;
#pragma unroll
    for (int off = 8; off > 0; off >>= 1) {
        p1 += __shfl_down_sync(0xFFFFFFFFu, p1, off, 16);
        p2 += __shfl_down_sync(0xFFFFFFFFu, p2, off, 16);
    }
    if ((threadIdx.x & 15) == 0) {
        g_s1[row] = p1;
        g_s2[row] = p2;
    }
}

// ---------------------------------------------------------------------------
// Histogram: degree per src node
// ---------------------------------------------------------------------------
__global__ void hist_kernel(const int* __restrict__ ei, int e) {
    int i = blockIdx.x * blockDim.x + threadIdx.x;
    if (i < e) atomicAdd(&g_deg[ei[i]], 1);
}

// ---------------------------------------------------------------------------
// Exclusive scan of g_deg -> g_off (3 stages)
// ---------------------------------------------------------------------------
__global__ void scan1_kernel(int n) {
    __shared__ int sh[SCAN_B];
    int t = threadIdx.x;
    int i = blockIdx.x * SCAN_B + t;
    int v = (i < n) ? g_deg[i] : 0;
    sh[t] = v;
    __syncthreads();
#pragma unroll
    for (int off = 1; off < SCAN_B; off <<= 1) {
        int add = (t >= off) ? sh[t - off] : 0;
        __syncthreads();
        sh[t] += add;
        __syncthreads();
    }
    if (i < n) g_off[i] = sh[t] - v;   // exclusive
    if (t == SCAN_B - 1) g_blksum[blockIdx.x] = sh[t];
}

__global__ void scan2_kernel(int nb) {
    if (threadIdx.x == 0) {
        int s = 0;
        for (int b = 0; b < nb; b++) {
            int t = g_blksum[b];
            g_blksum[b] = s;
            s += t;
        }
    }
}

__global__ void scan3_kernel(int n) {
    int i = blockIdx.x * blockDim.x + threadIdx.x;
    if (i < n) {
        g_off[i] += g_blksum[i >> 10];
        g_deg[i] = 0;  // reset for use as scatter cursor
    }
}

// ---------------------------------------------------------------------------
// Scatter: place (dst, weight) into CSR slot; weight computed here.
// ---------------------------------------------------------------------------
__global__ void scatter_kernel(const int* __restrict__ ei, int e) {
    int i = blockIdx.x * blockDim.x + threadIdx.x;
    if (i >= e) return;
    int src = ei[i];
    int dst = ei[e + i];
    float logit = g_s1[src] + g_s2[dst];
    float l = logit > 0.0f ? logit : ALPHA * logit;
    float w = __expf(-l);
    int pos = g_off[src] + atomicAdd(&g_deg[src], 1);
    g_csr[pos] = make_float2(__int_as_float(dst), w);
}

// ---------------------------------------------------------------------------
// Aggregate: warp per node, gather-accumulate from CSR, fused normalize+elu.
// ---------------------------------------------------------------------------
__global__ void agg_kernel(float* __restrict__ out, int n) {
    int warp = (blockIdx.x * blockDim.x + threadIdx.x) >> 5;
    int lane = threadIdx.x & 31;
    if (warp >= n) return;

    int start = g_off[warp];
    int len   = g_deg[warp];

    float acc0 = 0.f, acc1 = 0.f, rs = 0.f;
    for (int k = 0; k < len; k++) {
        float2 ew = g_csr[start + k];
        int dst  = __float_as_int(ew.x);
        float w  = ew.y;
        acc0 += w * g_h[(size_t)dst * OUT + lane];
        acc1 += w * g_h[(size_t)dst * OUT + 32 + lane];
        rs   += w;
    }
    float inv = 1.0f / rs;
    float v0 = acc0 * inv;
    float v1 = acc1 * inv;
    out[(size_t)warp * OUT + lane]      = v0 > 0.0f ? v0 : expm1f(v0);
    out[(size_t)warp * OUT + 32 + lane] = v1 > 0.0f ? v1 : expm1f(v1);
}

extern "C" void kernel_launch(void* const* d_in, const int* in_sizes, int n_in,
                              void* d_out, int out_size) {
    const float* x  = (const float*)d_in[0];
    const int*   ei = (const int*)d_in[1];
    const float* W  = (const float*)d_in[2];
    const float* a  = (const float*)d_in[3];
    float* out = (float*)d_out;

    int n = in_sizes[0] / DIM;   // 50000
    int e = in_sizes[1] / 2;     // 1600000
    int nb = (n + SCAN_B - 1) / SCAN_B;

    zero_deg_kernel<<<(n + 255) / 256, 256>>>(n);
    gemm_kernel<<<(n * 16 + 255) / 256, 256>>>(x, W, a, n);
    hist_kernel<<<(e + 255) / 256, 256>>>(ei, e);
    scan1_kernel<<<nb, SCAN_B>>>(n);
    scan2_kernel<<<1, 32>>>(nb);
    scan3_kernel<<<(n + 255) / 256, 256>>>(n);
    scatter_kernel<<<(e + 255) / 256, 256>>>(ei, e);
    agg_kernel<<<(n * 32 + 255) / 256, 256>>>(out, n);
}

// round 3
// speedup vs baseline: 1.7762x; 1.2922x over previous
#include <cuda_runtime.h>
#include <cuda_bf16.h>

#define DIM 256
#define OUT 64
#define ALPHA 0.2f
#define N_MAX 50048
#define E_MAX 1600000
#define SCAN_B 1024
#define MAX_SCAN_BLOCKS ((N_MAX + SCAN_B - 1) / SCAN_B)

// Scratch (device globals — no allocation allowed)
__device__ float g_h[N_MAX * OUT];
__device__ float g_s1[N_MAX];
__device__ float g_s2[N_MAX];
__device__ int   g_deg[N_MAX];               // histogram / scatter cursor / length
__device__ int   g_off[N_MAX];               // CSR exclusive offsets
__device__ int   g_blksum[MAX_SCAN_BLOCKS];
__device__ int   g_csr[E_MAX];               // dst indices grouped by src

// ---------------------------------------------------------------------------
// Packed fp32x2 helpers (Blackwell FFMA2 — only reachable via PTX)
// ---------------------------------------------------------------------------
__device__ __forceinline__ unsigned long long pack2(float lo, float hi) {
    unsigned long long r;
    asm("mov.b64 %0, {%1, %2};" : "=l"(r) : "f"(lo), "f"(hi));
    return r;
}
__device__ __forceinline__ void unpack2(unsigned long long v, float& lo, float& hi) {
    asm("mov.b64 {%0, %1}, %2;" : "=f"(lo), "=f"(hi) : "l"(v));
}
__device__ __forceinline__ void ffma2(unsigned long long& acc,
                                      unsigned long long a, unsigned long long b) {
    asm("fma.rn.f32x2 %0, %1, %2, %0;" : "+l"(acc) : "l"(a), "l"(b));
}

// ---------------------------------------------------------------------------
// Zero degree counters
// ---------------------------------------------------------------------------
__global__ void zero_deg_kernel(int n) {
    int i = blockIdx.x * blockDim.x + threadIdx.x;
    if (i < n) g_deg[i] = 0;
}

// ---------------------------------------------------------------------------
// h = x @ W with fused scores. 8 threads per 4-row group; each thread: 8 cols.
// W read as ulonglong2 (pre-packed f32x2 pairs). x broadcast across the group.
// ---------------------------------------------------------------------------
__global__ void gemm_kernel(const float* __restrict__ x,
                            const float* __restrict__ W,
                            const float* __restrict__ a,
                            int n) {
    int gid = blockIdx.x * blockDim.x + threadIdx.x;
    int grp = gid >> 3;          // 4-row group index
    int cb  = (gid & 7) << 3;    // column base (0,8,...,56)
    int r0  = grp << 2;
    if (r0 >= n) return;

    int r1 = min(r0 + 1, n - 1);
    int r2 = min(r0 + 2, n - 1);
    int r3 = min(r0 + 3, n - 1);
    const float4* xp[4] = {
        reinterpret_cast<const float4*>(x + (size_t)r0 * DIM),
        reinterpret_cast<const float4*>(x + (size_t)r1 * DIM),
        reinterpret_cast<const float4*>(x + (size_t)r2 * DIM),
        reinterpret_cast<const float4*>(x + (size_t)r3 * DIM)};

    unsigned long long acc[4][4];
#pragma unroll
    for (int r = 0; r < 4; r++)
#pragma unroll
        for (int p = 0; p < 4; p++) acc[r][p] = 0ULL;  // bits of (0.f, 0.f)

    for (int d4 = 0; d4 < DIM / 4; d4++) {
        float xs[4][4];
#pragma unroll
        for (int r = 0; r < 4; r++) {
            float4 xv = xp[r][d4];
            xs[r][0] = xv.x; xs[r][1] = xv.y; xs[r][2] = xv.z; xs[r][3] = xv.w;
        }
#pragma unroll
        for (int dd = 0; dd < 4; dd++) {
            int d = (d4 << 2) + dd;
            const ulonglong2* wp =
                reinterpret_cast<const ulonglong2*>(W + (size_t)d * OUT + cb);
            ulonglong2 wA = wp[0];   // cols cb+0..3 as two f32x2
            ulonglong2 wB = wp[1];   // cols cb+4..7
#pragma unroll
            for (int r = 0; r < 4; r++) {
                unsigned long long xx = pack2(xs[r][dd], xs[r][dd]);
                ffma2(acc[r][0], wA.x, xx);
                ffma2(acc[r][1], wA.y, xx);
                ffma2(acc[r][2], wB.x, xx);
                ffma2(acc[r][3], wB.y, xx);
            }
        }
    }

    // a slices for fused scores
    float a1v[8], a2v[8];
#pragma unroll
    for (int c = 0; c < 8; c++) {
        a1v[c] = a[cb + c];
        a2v[c] = a[OUT + cb + c];
    }

#pragma unroll
    for (int r = 0; r < 4; r++) {
        int row = r0 + r;
        if (row >= n) break;
        float o[8];
        unpack2(acc[r][0], o[0], o[1]);
        unpack2(acc[r][1], o[2], o[3]);
        unpack2(acc[r][2], o[4], o[5]);
        unpack2(acc[r][3], o[6], o[7]);

        *reinterpret_cast<float4*>(g_h + (size_t)row * OUT + cb) =
            make_float4(o[0], o[1], o[2], o[3]);
        *reinterpret_cast<float4*>(g_h + (size_t)row * OUT + cb + 4) =
            make_float4(o[4], o[5], o[6], o[7]);

        float p1 = 0.f, p2 = 0.f;
#pragma unroll
        for (int c = 0; c < 8; c++) {
            p1 += o[c] * a1v[c];
            p2 += o[c] * a2v[c];
        }
#pragma unroll
        for (int off = 4; off > 0; off >>= 1) {
            p1 += __shfl_down_sync(0xFFFFFFFFu, p1, off, 8);
            p2 += __shfl_down_sync(0xFFFFFFFFu, p2, off, 8);
        }
        if ((gid & 7) == 0) {
            g_s1[row] = p1;
            g_s2[row] = p2;
        }
    }
}

// ---------------------------------------------------------------------------
// Histogram: degree per src node
// ---------------------------------------------------------------------------
__global__ void hist_kernel(const int* __restrict__ ei, int e) {
    int i = blockIdx.x * blockDim.x + threadIdx.x;
    if (i < e) atomicAdd(&g_deg[ei[i]], 1);
}

// ---------------------------------------------------------------------------
// Exclusive scan of g_deg -> g_off (shuffle-based)
// ---------------------------------------------------------------------------
__global__ void scan1_kernel(int n) {
    int t = threadIdx.x, lane = t & 31, wid = t >> 5;
    int i = blockIdx.x * SCAN_B + t;
    int v = (i < n) ? g_deg[i] : 0;
    int xv = v;
#pragma unroll
    for (int off = 1; off < 32; off <<= 1) {
        int y = __shfl_up_sync(0xFFFFFFFFu, xv, off);
        if (lane >= off) xv += y;
    }
    __shared__ int wsum[32];
    if (lane == 31) wsum[wid] = xv;
    __syncthreads();
    if (wid == 0) {
        int s = wsum[lane];
#pragma unroll
        for (int off = 1; off < 32; off <<= 1) {
            int y = __shfl_up_sync(0xFFFFFFFFu, s, off);
            if (lane >= off) s += y;
        }
        wsum[lane] = s;
    }
    __syncthreads();
    int incl = xv + (wid ? wsum[wid - 1] : 0);
    if (i < n) g_off[i] = incl - v;
    if (t == SCAN_B - 1) g_blksum[blockIdx.x] = incl;
}

__global__ void scan2_kernel(int nb) {
    __shared__ int sh[64];
    int t = threadIdx.x;
    int v = (t < nb) ? g_blksum[t] : 0;
    sh[t] = v;
    __syncthreads();
#pragma unroll
    for (int off = 1; off < 64; off <<= 1) {
        int add = (t >= off) ? sh[t - off] : 0;
        __syncthreads();
        sh[t] += add;
        __syncthreads();
    }
    if (t < nb) g_blksum[t] = sh[t] - v;  // exclusive
}

__global__ void scan3_kernel(int n) {
    int i = blockIdx.x * blockDim.x + threadIdx.x;
    if (i < n) {
        g_off[i] += g_blksum[i >> 10];
        g_deg[i] = 0;  // reset for scatter cursor
    }
}

// ---------------------------------------------------------------------------
// Scatter: dst index only into CSR slot
// ---------------------------------------------------------------------------
__global__ void scatter_kernel(const int* __restrict__ ei, int e) {
    int i = blockIdx.x * blockDim.x + threadIdx.x;
    if (i >= e) return;
    int src = ei[i];
    int dst = ei[e + i];
    int pos = g_off[src] + atomicAdd(&g_deg[src], 1);
    g_csr[pos] = dst;
}

// ---------------------------------------------------------------------------
// Aggregate: warp per node. Weights computed lane-parallel (32 edges at once),
// then shuffled into the gather-accumulate loop. Fused normalize + elu.
// ---------------------------------------------------------------------------
__global__ void agg_kernel(float* __restrict__ out, int n) {
    int warp = (blockIdx.x * blockDim.x + threadIdx.x) >> 5;
    int lane = threadIdx.x & 31;
    if (warp >= n) return;

    int start = g_off[warp];
    int len   = g_deg[warp];
    float s1n = g_s1[warp];

    float acc0 = 0.f, acc1 = 0.f, wsum = 0.f;

    for (int base = 0; base < len; base += 32) {
        int k = base + lane;
        int dstl = 0;
        float wl = 0.f;
        if (k < len) {
            dstl = g_csr[start + k];
            float lg = s1n + g_s2[dstl];
            float lr = lg > 0.f ? lg : ALPHA * lg;
            wl = __expf(-lr);
        }
        wsum += wl;
        int m = len - base;
        if (m >= 32) {
#pragma unroll 8
            for (int j = 0; j < 32; j++) {
                int   d = __shfl_sync(0xFFFFFFFFu, dstl, j);
                float w = __shfl_sync(0xFFFFFFFFu, wl, j);
                acc0 += w * g_h[(size_t)d * OUT + lane];
                acc1 += w * g_h[(size_t)d * OUT + 32 + lane];
            }
        } else {
            for (int j = 0; j < m; j++) {
                int   d = __shfl_sync(0xFFFFFFFFu, dstl, j);
                float w = __shfl_sync(0xFFFFFFFFu, wl, j);
                acc0 += w * g_h[(size_t)d * OUT + lane];
                acc1 += w * g_h[(size_t)d * OUT + 32 + lane];
            }
        }
    }

#pragma unroll
    for (int off = 16; off > 0; off >>= 1)
        wsum += __shfl_xor_sync(0xFFFFFFFFu, wsum, off);

    float inv = 1.0f / wsum;
    float v0 = acc0 * inv;
    float v1 = acc1 * inv;
    out[(size_t)warp * OUT + lane]      = v0 > 0.f ? v0 : expm1f(v0);
    out[(size_t)warp * OUT + 32 + lane] = v1 > 0.f ? v1 : expm1f(v1);
}

extern "C" void kernel_launch(void* const* d_in, const int* in_sizes, int n_in,
                              void* d_out, int out_size) {
    const float* x  = (const float*)d_in[0];
    const int*   ei = (const int*)d_in[1];
    const float* W  = (const float*)d_in[2];
    const float* a  = (const float*)d_in[3];
    float* out = (float*)d_out;

    int n = in_sizes[0] / DIM;   // 50000
    int e = in_sizes[1] / 2;     // 1600000
    int nb = (n + SCAN_B - 1) / SCAN_B;

    zero_deg_kernel<<<(n + 255) / 256, 256>>>(n);

    int gemm_threads = ((n + 3) / 4) * 8;
    gemm_kernel<<<(gemm_threads + 255) / 256, 256>>>(x, W, a, n);

    hist_kernel<<<(e + 255) / 256, 256>>>(ei, e);
    scan1_kernel<<<nb, SCAN_B>>>(n);
    scan2_kernel<<<1, 64>>>(nb);
    scan3_kernel<<<(n + 255) / 256, 256>>>(n);
    scatter_kernel<<<(e + 255) / 256, 256>>>(ei, e);

    agg_kernel<<<((long long)n * 32 + 255) / 256, 256>>>(out, n);
}

// round 4
// speedup vs baseline: 1.9809x; 1.1152x over previous
#include <cuda_runtime.h>
#include <cuda_fp16.h>
#include <cuda_bf16.h>

#define DIM 256
#define OUT 64
#define ALPHA 0.2f
#define N_MAX 50048
#define E_MAX 1600000
#define SCAN_B 1024
#define MAX_SCAN_BLOCKS ((N_MAX + SCAN_B - 1) / SCAN_B)

// Scratch (device globals — no allocation allowed)
__device__ __half g_h[N_MAX * OUT];          // h = x @ W (fp16; consumed only by agg)
__device__ float  g_s1[N_MAX];
__device__ float  g_s2[N_MAX];
__device__ int    g_deg[N_MAX];              // histogram (kept as CSR lengths)
__device__ int    g_cur[N_MAX];              // scatter cursor
__device__ int    g_off[N_MAX];              // block-local exclusive offsets
__device__ int    g_blksum[MAX_SCAN_BLOCKS]; // exclusive block sums
__device__ int    g_csr[E_MAX];              // dst indices grouped by src

// ---------------------------------------------------------------------------
// Packed fp32x2 helpers (Blackwell FFMA2 — only reachable via PTX)
// ---------------------------------------------------------------------------
__device__ __forceinline__ unsigned long long pack2(float lo, float hi) {
    unsigned long long r;
    asm("mov.b64 %0, {%1, %2};" : "=l"(r) : "f"(lo), "f"(hi));
    return r;
}
__device__ __forceinline__ void unpack2(unsigned long long v, float& lo, float& hi) {
    asm("mov.b64 {%0, %1}, %2;" : "=f"(lo), "=f"(hi) : "l"(v));
}
__device__ __forceinline__ void ffma2(unsigned long long& acc,
                                      unsigned long long a, unsigned long long b) {
    asm("fma.rn.f32x2 %0, %1, %2, %0;" : "+l"(acc) : "l"(a), "l"(b));
}

// ---------------------------------------------------------------------------
// Zero degree + cursor
// ---------------------------------------------------------------------------
__global__ void zero_kernel(int n) {
    int i = blockIdx.x * blockDim.x + threadIdx.x;
    if (i < n) {
        g_deg[i] = 0;
        g_cur[i] = 0;
    }
}

// ---------------------------------------------------------------------------
// h = x @ W with fused scores. 8 threads per 4-row group; each thread: 8 cols.
// fp32x2 FMA mainloop; fp16 store of h; fp32 scores.
// ---------------------------------------------------------------------------
__global__ void gemm_kernel(const float* __restrict__ x,
                            const float* __restrict__ W,
                            const float* __restrict__ a,
                            int n) {
    int gid = blockIdx.x * blockDim.x + threadIdx.x;
    int grp = gid >> 3;          // 4-row group index
    int cb  = (gid & 7) << 3;    // column base (0,8,...,56)
    int r0  = grp << 2;
    if (r0 >= n) return;

    int r1 = min(r0 + 1, n - 1);
    int r2 = min(r0 + 2, n - 1);
    int r3 = min(r0 + 3, n - 1);
    const float4* xp[4] = {
        reinterpret_cast<const float4*>(x + (size_t)r0 * DIM),
        reinterpret_cast<const float4*>(x + (size_t)r1 * DIM),
        reinterpret_cast<const float4*>(x + (size_t)r2 * DIM),
        reinterpret_cast<const float4*>(x + (size_t)r3 * DIM)};

    unsigned long long acc[4][4];
#pragma unroll
    for (int r = 0; r < 4; r++)
#pragma unroll
        for (int p = 0; p < 4; p++) acc[r][p] = 0ULL;

    for (int d4 = 0; d4 < DIM / 4; d4++) {
        float xs[4][4];
#pragma unroll
        for (int r = 0; r < 4; r++) {
            float4 xv = xp[r][d4];
            xs[r][0] = xv.x; xs[r][1] = xv.y; xs[r][2] = xv.z; xs[r][3] = xv.w;
        }
#pragma unroll
        for (int dd = 0; dd < 4; dd++) {
            int d = (d4 << 2) + dd;
            const ulonglong2* wp =
                reinterpret_cast<const ulonglong2*>(W + (size_t)d * OUT + cb);
            ulonglong2 wA = wp[0];
            ulonglong2 wB = wp[1];
#pragma unroll
            for (int r = 0; r < 4; r++) {
                unsigned long long xx = pack2(xs[r][dd], xs[r][dd]);
                ffma2(acc[r][0], wA.x, xx);
                ffma2(acc[r][1], wA.y, xx);
                ffma2(acc[r][2], wB.x, xx);
                ffma2(acc[r][3], wB.y, xx);
            }
        }
    }

    float a1v[8], a2v[8];
#pragma unroll
    for (int c = 0; c < 8; c++) {
        a1v[c] = a[cb + c];
        a2v[c] = a[OUT + cb + c];
    }

#pragma unroll
    for (int r = 0; r < 4; r++) {
        int row = r0 + r;
        if (row >= n) break;
        float o[8];
        unpack2(acc[r][0], o[0], o[1]);
        unpack2(acc[r][1], o[2], o[3]);
        unpack2(acc[r][2], o[4], o[5]);
        unpack2(acc[r][3], o[6], o[7]);

        // fp16 store: 8 cols = 16B = one uint4
        __half2 hp[4];
#pragma unroll
        for (int p = 0; p < 4; p++)
            hp[p] = __floats2half2_rn(o[2 * p], o[2 * p + 1]);
        *reinterpret_cast<uint4*>(g_h + (size_t)row * OUT + cb) =
            *reinterpret_cast<uint4*>(hp);

        float p1 = 0.f, p2 = 0.f;
#pragma unroll
        for (int c = 0; c < 8; c++) {
            p1 += o[c] * a1v[c];
            p2 += o[c] * a2v[c];
        }
#pragma unroll
        for (int off = 4; off > 0; off >>= 1) {
            p1 += __shfl_down_sync(0xFFFFFFFFu, p1, off, 8);
            p2 += __shfl_down_sync(0xFFFFFFFFu, p2, off, 8);
        }
        if ((gid & 7) == 0) {
            g_s1[row] = p1;
            g_s2[row] = p2;
        }
    }
}

// ---------------------------------------------------------------------------
// Histogram: degree per src node
// ---------------------------------------------------------------------------
__global__ void hist_kernel(const int* __restrict__ ei, int e) {
    int i = blockIdx.x * blockDim.x + threadIdx.x;
    if (i < e) atomicAdd(&g_deg[ei[i]], 1);
}

// ---------------------------------------------------------------------------
// Scan stage 1: block-local exclusive scan (shuffle-based)
// ---------------------------------------------------------------------------
__global__ void scan1_kernel(int n) {
    int t = threadIdx.x, lane = t & 31, wid = t >> 5;
    int i = blockIdx.x * SCAN_B + t;
    int v = (i < n) ? g_deg[i] : 0;
    int xv = v;
#pragma unroll
    for (int off = 1; off < 32; off <<= 1) {
        int y = __shfl_up_sync(0xFFFFFFFFu, xv, off);
        if (lane >= off) xv += y;
    }
    __shared__ int wsum[32];
    if (lane == 31) wsum[wid] = xv;
    __syncthreads();
    if (wid == 0) {
        int s = wsum[lane];
#pragma unroll
        for (int off = 1; off < 32; off <<= 1) {
            int y = __shfl_up_sync(0xFFFFFFFFu, s, off);
            if (lane >= off) s += y;
        }
        wsum[lane] = s;
    }
    __syncthreads();
    int incl = xv + (wid ? wsum[wid - 1] : 0);
    if (i < n) g_off[i] = incl - v;
    if (t == SCAN_B - 1) g_blksum[blockIdx.x] = incl;
}

// ---------------------------------------------------------------------------
// Scan stage 2: exclusive scan of block sums (single block)
// ---------------------------------------------------------------------------
__global__ void scan2_kernel(int nb) {
    __shared__ int sh[64];
    int t = threadIdx.x;
    int v = (t < nb) ? g_blksum[t] : 0;
    sh[t] = v;
    __syncthreads();
#pragma unroll
    for (int off = 1; off < 64; off <<= 1) {
        int add = (t >= off) ? sh[t - off] : 0;
        __syncthreads();
        sh[t] += add;
        __syncthreads();
    }
    if (t < nb) g_blksum[t] = sh[t] - v;  // exclusive
}

// ---------------------------------------------------------------------------
// Scatter: dst index only into CSR slot (offset = local + block base)
// ---------------------------------------------------------------------------
__global__ void scatter_kernel(const int* __restrict__ ei, int e) {
    int i = blockIdx.x * blockDim.x + threadIdx.x;
    if (i >= e) return;
    int src = ei[i];
    int dst = ei[e + i];
    int pos = g_off[src] + g_blksum[src >> 10] + atomicAdd(&g_cur[src], 1);
    g_csr[pos] = dst;
}

// ---------------------------------------------------------------------------
// Aggregate: warp per node. Weights computed lane-parallel, gather fp16 h.
// One LDG.32 + one 128B L2 line per edge. Fused normalize + elu.
// ---------------------------------------------------------------------------
__global__ void agg_kernel(float* __restrict__ out, int n) {
    int warp = (blockIdx.x * blockDim.x + threadIdx.x) >> 5;
    int lane = threadIdx.x & 31;
    if (warp >= n) return;

    int start = g_off[warp] + g_blksum[warp >> 10];
    int len   = g_deg[warp];
    float s1n = g_s1[warp];

    float acc0 = 0.f, acc1 = 0.f, wsum = 0.f;

    for (int base = 0; base < len; base += 32) {
        int k = base + lane;
        int dstl = 0;
        float wl = 0.f;
        if (k < len) {
            dstl = g_csr[start + k];
            float lg = s1n + g_s2[dstl];
            float lr = lg > 0.f ? lg : ALPHA * lg;
            wl = __expf(-lr);
        }
        wsum += wl;
        int m = len - base;
        if (m >= 32) {
#pragma unroll 8
            for (int j = 0; j < 32; j++) {
                int   d = __shfl_sync(0xFFFFFFFFu, dstl, j);
                float w = __shfl_sync(0xFFFFFFFFu, wl, j);
                __half2 hv = *reinterpret_cast<const __half2*>(
                    g_h + (size_t)d * OUT + lane * 2);
                float2 f = __half22float2(hv);
                acc0 += w * f.x;
                acc1 += w * f.y;
            }
        } else {
            for (int j = 0; j < m; j++) {
                int   d = __shfl_sync(0xFFFFFFFFu, dstl, j);
                float w = __shfl_sync(0xFFFFFFFFu, wl, j);
                __half2 hv = *reinterpret_cast<const __half2*>(
                    g_h + (size_t)d * OUT + lane * 2);
                float2 f = __half22float2(hv);
                acc0 += w * f.x;
                acc1 += w * f.y;
            }
        }
    }

#pragma unroll
    for (int off = 16; off > 0; off >>= 1)
        wsum += __shfl_xor_sync(0xFFFFFFFFu, wsum, off);

    float inv = 1.0f / wsum;
    float v0 = acc0 * inv;
    float v1 = acc1 * inv;
    // lane covers cols (2*lane, 2*lane+1)
    out[(size_t)warp * OUT + lane * 2]     = v0 > 0.f ? v0 : expm1f(v0);
    out[(size_t)warp * OUT + lane * 2 + 1] = v1 > 0.f ? v1 : expm1f(v1);
}

extern "C" void kernel_launch(void* const* d_in, const int* in_sizes, int n_in,
                              void* d_out, int out_size) {
    const float* x  = (const float*)d_in[0];
    const int*   ei = (const int*)d_in[1];
    const float* W  = (const float*)d_in[2];
    const float* a  = (const float*)d_in[3];
    float* out = (float*)d_out;

    int n = in_sizes[0] / DIM;   // 50000
    int e = in_sizes[1] / 2;     // 1600000
    int nb = (n + SCAN_B - 1) / SCAN_B;

    zero_kernel<<<(n + 255) / 256, 256>>>(n);

    int gemm_threads = ((n + 3) / 4) * 8;
    gemm_kernel<<<(gemm_threads + 255) / 256, 256>>>(x, W, a, n);

    hist_kernel<<<(e + 255) / 256, 256>>>(ei, e);
    scan1_kernel<<<nb, SCAN_B>>>(n);
    scan2_kernel<<<1, 64>>>(nb);
    scatter_kernel<<<(e + 255) / 256, 256>>>(ei, e);

    agg_kernel<<<((long long)n * 32 + 255) / 256, 256>>>(out, n);
}